// round 14
// baseline (speedup 1.0000x reference)
#include <cuda_runtime.h>
#include <cuda_fp16.h>
#include <math.h>

#define N_NODES   100000
#define N_EDGES   3200000
#define NODE_DIM  128
#define HID       16
#define N_GRAPHS  256
#define MRI_DIM   256
#define COG_DIM   64
#define CLIN_DIM  32
#define GEN_DIM   512

#define NODECAP   96               // max in-degree kept (Poisson(32): P(>96) ~ 1e-20)

// ---------------- device scratch ---------------------------------------------
__device__ __half g_xwh[(size_t)N_NODES * HID];        // (x@W) * dinv (fp16 rows)
__device__ float  g_agg[(size_t)N_NODES * HID];        // relu(gcn output)
__device__ float  g_dinv[N_NODES];
__device__ int    g_cur[N_NODES];                      // degree cursor (zero-init; kB resets)
__device__ int    g_nbuf[(size_t)N_NODES * NODECAP];   // per-node src arenas

// ---------------- pass A: direct node-grouped scatter (one atomic/edge) -------
__global__ __launch_bounds__(256) void kA(const int* __restrict__ ei,
                                          int e0, int ecount) {
    int i = blockIdx.x * blockDim.x + threadIdx.x;
    if (i >= ecount / 4) return;
    const int4* s4 = reinterpret_cast<const int4*>(ei + e0);
    const int4* d4 = reinterpret_cast<const int4*>(ei + N_EDGES + e0);
    int4 s = __ldg(&s4[i]);
    int4 d = __ldg(&d4[i]);
    int p;
    p = atomicAdd(&g_cur[d.x], 1); if (p < NODECAP) g_nbuf[(size_t)d.x * NODECAP + p] = s.x;
    p = atomicAdd(&g_cur[d.y], 1); if (p < NODECAP) g_nbuf[(size_t)d.y * NODECAP + p] = s.y;
    p = atomicAdd(&g_cur[d.z], 1); if (p < NODECAP) g_nbuf[(size_t)d.z * NODECAP + p] = s.z;
    p = atomicAdd(&g_cur[d.w], 1); if (p < NODECAP) g_nbuf[(size_t)d.w * NODECAP + p] = s.w;
}

// ---------------- xw = x @ W, dinv from g_cur, fp16 premultiplied rows --------
__global__ __launch_bounds__(256) void k_xw(const float* __restrict__ x,
                                            const float* __restrict__ W) {
    __shared__ float4 sW4[16 * 32];
    for (int q = threadIdx.x; q < 512; q += 256) {
        int c = q >> 5, f = q & 31;
        sW4[q] = make_float4(W[(4 * f + 0) * HID + c], W[(4 * f + 1) * HID + c],
                             W[(4 * f + 2) * HID + c], W[(4 * f + 3) * HID + c]);
    }
    __syncthreads();

    int warp = (blockIdx.x * blockDim.x + threadIdx.x) >> 5;
    int lane = threadIdx.x & 31;
    int row  = warp * 4 + (lane >> 3);
    int sub  = lane & 7;
    if (row >= N_NODES) return;

    const float4* xr = reinterpret_cast<const float4*>(x + (size_t)row * NODE_DIM);
    float acc[16];
#pragma unroll
    for (int c = 0; c < 16; c++) acc[c] = 0.0f;

#pragma unroll
    for (int i = 0; i < 4; i++) {
        float4 xv = __ldg(&xr[sub * 4 + i]);
        int f = sub * 4 + i;
#pragma unroll
        for (int c = 0; c < 16; c++) {
            float4 wv = sW4[c * 32 + f];
            acc[c] += xv.x * wv.x + xv.y * wv.y + xv.z * wv.z + xv.w * wv.w;
        }
    }
#pragma unroll
    for (int off = 4; off; off >>= 1)
#pragma unroll
        for (int c = 0; c < 16; c++)
            acc[c] += __shfl_xor_sync(0xffffffffu, acc[c], off);

    if (sub == 0) {
        int deg = g_cur[row];                   // final cursor = in-degree
        float di = rsqrtf((float)(deg + 1));    // +1 self loop
        g_dinv[row] = di;
        __half2 h[8];
#pragma unroll
        for (int k = 0; k < 8; k++)
            h[k] = __floats2half2_rn(acc[2 * k] * di, acc[2 * k + 1] * di);
        uint4* o = reinterpret_cast<uint4*>(&g_xwh[(size_t)row * HID]);
        o[0] = *reinterpret_cast<uint4*>(&h[0]);
        o[1] = *reinterpret_cast<uint4*>(&h[4]);
    }
}

// ---------------- pass B: pure gather-reduce (warp per node) + finalize -------
__global__ __launch_bounds__(512) void kB(const float* __restrict__ bias) {
    int node = (blockIdx.x * 512 + threadIdx.x) >> 5;
    if (node >= N_NODES) return;
    int lane = threadIdx.x & 31;
    int sub = lane >> 2, part = lane & 3;

    int deg = g_cur[node];                     // broadcast load
    if (lane == 0) g_cur[node] = 0;            // reset for next graph replay
    if (deg > NODECAP) deg = NODECAP;

    const int* list = &g_nbuf[(size_t)node * NODECAP];
    const uint2* xh = reinterpret_cast<const uint2*>(g_xwh);

    float4 acc  = make_float4(0.f, 0.f, 0.f, 0.f);
    float4 acc2 = make_float4(0.f, 0.f, 0.f, 0.f);
    int e = sub;
    // 4-deep unroll: 4 independent gathers in flight
    for (; e + 24 < deg; e += 32) {
        int s0 = __ldg(&list[e]);
        int s1 = __ldg(&list[e + 8]);
        int s2 = __ldg(&list[e + 16]);
        int s3 = __ldg(&list[e + 24]);
        uint2 r0 = __ldg(&xh[(size_t)s0 * 4 + part]);
        uint2 r1 = __ldg(&xh[(size_t)s1 * 4 + part]);
        uint2 r2 = __ldg(&xh[(size_t)s2 * 4 + part]);
        uint2 r3 = __ldg(&xh[(size_t)s3 * 4 + part]);
        float2 a, b;
        a = __half22float2(*reinterpret_cast<const __half2*>(&r0.x));
        b = __half22float2(*reinterpret_cast<const __half2*>(&r0.y));
        acc.x += a.x; acc.y += a.y; acc.z += b.x; acc.w += b.y;
        a = __half22float2(*reinterpret_cast<const __half2*>(&r1.x));
        b = __half22float2(*reinterpret_cast<const __half2*>(&r1.y));
        acc2.x += a.x; acc2.y += a.y; acc2.z += b.x; acc2.w += b.y;
        a = __half22float2(*reinterpret_cast<const __half2*>(&r2.x));
        b = __half22float2(*reinterpret_cast<const __half2*>(&r2.y));
        acc.x += a.x; acc.y += a.y; acc.z += b.x; acc.w += b.y;
        a = __half22float2(*reinterpret_cast<const __half2*>(&r3.x));
        b = __half22float2(*reinterpret_cast<const __half2*>(&r3.y));
        acc2.x += a.x; acc2.y += a.y; acc2.z += b.x; acc2.w += b.y;
    }
    for (; e < deg; e += 8) {
        int s0 = __ldg(&list[e]);
        uint2 r0 = __ldg(&xh[(size_t)s0 * 4 + part]);
        float2 a = __half22float2(*reinterpret_cast<const __half2*>(&r0.x));
        float2 b = __half22float2(*reinterpret_cast<const __half2*>(&r0.y));
        acc.x += a.x; acc.y += a.y; acc.z += b.x; acc.w += b.y;
    }
    acc.x += acc2.x; acc.y += acc2.y; acc.z += acc2.z; acc.w += acc2.w;

#pragma unroll
    for (int o = 4; o <= 16; o <<= 1) {
        acc.x += __shfl_xor_sync(0xffffffffu, acc.x, o);
        acc.y += __shfl_xor_sync(0xffffffffu, acc.y, o);
        acc.z += __shfl_xor_sync(0xffffffffu, acc.z, o);
        acc.w += __shfl_xor_sync(0xffffffffu, acc.w, o);
    }
    if (lane < 4) {
        uint2 rw = xh[(size_t)node * 4 + lane];            // self term (premult)
        float2 f0 = __half22float2(*reinterpret_cast<const __half2*>(&rw.x));
        float2 f1 = __half22float2(*reinterpret_cast<const __half2*>(&rw.y));
        float di = g_dinv[node];
        float4 bv = __ldg(&reinterpret_cast<const float4*>(bias)[lane]);
        float4 o;
        o.x = fmaxf((acc.x + f0.x) * di + bv.x, 0.0f);
        o.y = fmaxf((acc.y + f0.y) * di + bv.y, 0.0f);
        o.z = fmaxf((acc.z + f1.x) * di + bv.z, 0.0f);
        o.w = fmaxf((acc.w + f1.y) * di + bv.w, 0.0f);
        reinterpret_cast<float4*>(g_agg)[(size_t)node * 4 + lane] = o;
    }
}

// ---------------- head: pool + modality FCs + classifier + log_softmax -------
__global__ __launch_bounds__(128) void k_head(
    const int* __restrict__ batch,
    const float* __restrict__ mri,  const float* __restrict__ cog,
    const float* __restrict__ clin, const float* __restrict__ gen,
    const float* __restrict__ mri_W, const float* __restrict__ mri_b,
    const float* __restrict__ cog_W, const float* __restrict__ cog_b,
    const float* __restrict__ clin_W, const float* __restrict__ clin_b,
    const float* __restrict__ gen_W, const float* __restrict__ gen_b,
    const float* __restrict__ W1, const float* __restrict__ b1,
    const float* __restrict__ W2, const float* __restrict__ b2,
    float* __restrict__ out)
{
    int g = blockIdx.x;
    int t = threadIdx.x;

    __shared__ int s_bounds[2];
    if (t < 2) {
        int target = g + t;
        int lo = 0, hi = N_NODES;
        while (lo < hi) {
            int mid = (lo + hi) >> 1;
            if (batch[mid] < target) lo = mid + 1; else hi = mid;
        }
        s_bounds[t] = lo;
    }
    __syncthreads();
    int start = s_bounds[0], end = s_bounds[1];

    float v[32];
#pragma unroll
    for (int j = 0; j < 32; j++) v[j] = 0.0f;

    for (int n = start + t; n < end; n += 128) {
        const float4* r = reinterpret_cast<const float4*>(&g_agg[(size_t)n * HID]);
        float4 a = r[0], b_ = r[1], c_ = r[2], d_ = r[3];
        v[0] += a.x;  v[1] += a.y;  v[2] += a.z;  v[3] += a.w;
        v[4] += b_.x; v[5] += b_.y; v[6] += b_.z; v[7] += b_.w;
        v[8] += c_.x; v[9] += c_.y; v[10]+= c_.z; v[11]+= c_.w;
        v[12]+= d_.x; v[13]+= d_.y; v[14]+= d_.z; v[15]+= d_.w;
    }
    {
        const float* row = mri + (size_t)g * MRI_DIM;
        for (int k = t; k < MRI_DIM; k += 128) {
            float x = __ldg(&row[k]);
#pragma unroll
            for (int c = 0; c < 4; c++) v[16 + c] += x * __ldg(&mri_W[k * 4 + c]);
        }
    }
    if (t < COG_DIM) {
        float x = __ldg(&cog[(size_t)g * COG_DIM + t]);
#pragma unroll
        for (int c = 0; c < 4; c++) v[20 + c] += x * __ldg(&cog_W[t * 4 + c]);
    }
    if (t < CLIN_DIM) {
        float x = __ldg(&clin[(size_t)g * CLIN_DIM + t]);
#pragma unroll
        for (int c = 0; c < 4; c++) v[24 + c] += x * __ldg(&clin_W[t * 4 + c]);
    }
    {
        const float* row = gen + (size_t)g * GEN_DIM;
        for (int k = t; k < GEN_DIM; k += 128) {
            float x = __ldg(&row[k]);
#pragma unroll
            for (int c = 0; c < 4; c++) v[28 + c] += x * __ldg(&gen_W[k * 4 + c]);
        }
    }

#pragma unroll
    for (int off = 16; off; off >>= 1)
#pragma unroll
        for (int j = 0; j < 32; j++)
            v[j] += __shfl_xor_sync(0xffffffffu, v[j], off);

    __shared__ float s_red[4][32];
    int warp = t >> 5, lane = t & 31;
    if (lane == 0)
#pragma unroll
        for (int j = 0; j < 32; j++) s_red[warp][j] = v[j];
    __syncthreads();

    __shared__ float s_comb[32];
    if (t < 32) {
        float val = s_red[0][t] + s_red[1][t] + s_red[2][t] + s_red[3][t];
        if (t < 16) {
            float cnt = fmaxf((float)(end - start), 1.0f);
            s_comb[t] = val / cnt;
        } else {
            int c = (t - 16) & 3;
            int m = (t - 16) >> 2;
            float bias = (m == 0) ? __ldg(&mri_b[c]) :
                         (m == 1) ? __ldg(&cog_b[c]) :
                         (m == 2) ? __ldg(&clin_b[c]) : __ldg(&gen_b[c]);
            s_comb[t] = fmaxf(val + bias, 0.0f);
        }
    }
    __syncthreads();

    __shared__ float s_h[16];
    if (t < 16) {
        float h = __ldg(&b1[t]);
#pragma unroll
        for (int i = 0; i < 32; i++) h += s_comb[i] * __ldg(&W1[i * 16 + t]);
        s_h[t] = fmaxf(h, 0.0f);
    }
    __syncthreads();

    __shared__ float s_lg[3];
    if (t < 3) {
        float lg = __ldg(&b2[t]);
#pragma unroll
        for (int j = 0; j < 16; j++) lg += s_h[j] * __ldg(&W2[j * 3 + t]);
        s_lg[t] = lg;
    }
    __syncthreads();

    if (t == 0) {
        float m = fmaxf(fmaxf(s_lg[0], s_lg[1]), s_lg[2]);
        float se = expf(s_lg[0] - m) + expf(s_lg[1] - m) + expf(s_lg[2] - m);
        float lse = m + logf(se);
        out[g * 3 + 0] = s_lg[0] - lse;
        out[g * 3 + 1] = s_lg[1] - lse;
        out[g * 3 + 2] = s_lg[2] - lse;
    }
}

// -----------------------------------------------------------------------------
extern "C" void kernel_launch(void* const* d_in, const int* in_sizes, int n_in,
                              void* d_out, int out_size) {
    const float* x      = (const float*)d_in[0];
    const int*   ei     = (const int*)d_in[1];
    const int*   batch  = (const int*)d_in[2];
    const float* mri    = (const float*)d_in[3];
    const float* cog    = (const float*)d_in[4];
    const float* clin   = (const float*)d_in[5];
    const float* gen    = (const float*)d_in[6];
    const float* gcn_W  = (const float*)d_in[7];
    const float* gcn_b  = (const float*)d_in[8];
    const float* mri_W  = (const float*)d_in[9];
    const float* mri_b  = (const float*)d_in[10];
    const float* cog_W  = (const float*)d_in[11];
    const float* cog_b  = (const float*)d_in[12];
    const float* clin_W = (const float*)d_in[13];
    const float* clin_b = (const float*)d_in[14];
    const float* gen_W  = (const float*)d_in[15];
    const float* gen_b  = (const float*)d_in[16];
    const float* W1     = (const float*)d_in[17];
    const float* b1     = (const float*)d_in[18];
    const float* W2     = (const float*)d_in[19];
    const float* b2     = (const float*)d_in[20];
    float* out = (float*)d_out;

    const int HALF = N_EDGES / 2;                                 // 1.6M
    kA<<<(HALF / 4 + 255) / 256, 256>>>(ei, 0, HALF);             // 1
    kA<<<(HALF / 4 + 255) / 256, 256>>>(ei, HALF, HALF);          // 2
    k_xw<<<(N_NODES + 31) / 32, 256>>>(x, gcn_W);                 // 3
    kB<<<(N_NODES * 32 + 511) / 512, 512>>>(gcn_b);               // 4  <- profiled
    k_head<<<N_GRAPHS, 128>>>(batch, mri, cog, clin, gen,         // 5
                              mri_W, mri_b, cog_W, cog_b, clin_W, clin_b,
                              gen_W, gen_b, W1, b1, W2, b2, out);
}

// round 15
// speedup vs baseline: 1.8898x; 1.8898x over previous
#include <cuda_runtime.h>
#include <cuda_fp16.h>
#include <math.h>

#define N_NODES   100000
#define N_EDGES   3200000
#define NODE_DIM  128
#define HID       16
#define N_GRAPHS  256
#define MRI_DIM   256
#define COG_DIM   64
#define CLIN_DIM  32
#define GEN_DIM   512

// bucketed counting sort
#define NBKT      512
#define BKT_NODES 196              // 511 buckets cover 100000 nodes
#define NBUSED    511
#define CAP       7680             // arena capacity per bucket (mean 6272, sigma ~79)
#define ABLK      800
#define AEDGES    4000             // 800 * 4000 = 3.2M exactly

// ---------------- device scratch ---------------------------------------------
__device__ __half        g_xwh[(size_t)N_NODES * HID]; // (x@W) * dinv (fp16 rows)
__device__ float         g_agg[(size_t)N_NODES * HID]; // relu(gcn output)
__device__ float         g_dinv[N_NODES];
__device__ int           g_deg[N_NODES];               // written fresh by kD
__device__ int           g_bcnt[NBKT];                 // arena counts (kD resets)
__device__ int           g_buf[(size_t)NBKT * CAP];    // packed (ldst<<17 | src)
__device__ unsigned char g_rank[(size_t)NBKT * CAP];   // within-node rank (kD)

// ---------------- pass A: in-smem bucket sort, coalesced arena writes ---------
__global__ __launch_bounds__(512) void kA(const int* __restrict__ ei) {
    __shared__ int            sp[AEDGES];
    __shared__ unsigned short sb[AEDGES];
    __shared__ int            sp2[AEDGES];
    __shared__ unsigned short sb2[AEDGES];
    __shared__ int hist[NBKT], startx[NBKT], cur[NBKT], basex[NBKT];
    __shared__ int wsum[16];

    int t = threadIdx.x;
    int lane = t & 31, w = t >> 5;
    int e0 = blockIdx.x * AEDGES;
    hist[t] = 0;
    __syncthreads();

    for (int i = t; i < AEDGES; i += 512) {
        int s = __ldg(&ei[e0 + i]);
        int d = __ldg(&ei[N_EDGES + e0 + i]);
        unsigned b = (unsigned)d / BKT_NODES;
        sp[i] = ((d - (int)b * BKT_NODES) << 17) | s;
        sb[i] = (unsigned short)b;
        atomicAdd(&hist[b], 1);
    }
    __syncthreads();

    // warp-shfl inclusive scan over 512 buckets
    int c = hist[t];
    int incl = c;
#pragma unroll
    for (int o = 1; o < 32; o <<= 1) {
        int u = __shfl_up_sync(0xffffffffu, incl, o);
        if (lane >= o) incl += u;
    }
    if (lane == 31) wsum[w] = incl;
    __syncthreads();
    int pre = 0;
#pragma unroll
    for (int k = 0; k < 16; k++) pre += (k < w) ? wsum[k] : 0;
    int excl = incl + pre - c;
    basex[t] = (c > 0) ? (t * CAP + atomicAdd(&g_bcnt[t], c)) : 0;  // arena claim
    cur[t] = excl;
    startx[t] = excl;
    __syncthreads();

    // place into smem sorted-by-bucket order
    for (int i = t; i < AEDGES; i += 512) {
        int b = sb[i];
        int r = atomicAdd(&cur[b], 1);
        sp2[r] = sp[i];
        sb2[r] = (unsigned short)b;
    }
    __syncthreads();

    // write out: consecutive j within a bucket run -> contiguous global span
    for (int j = t; j < AEDGES; j += 512) {
        int b = sb2[j];
        int pos = basex[b] + (j - startx[b]);
        if (pos < (b + 1) * CAP) g_buf[pos] = sp2[j];
    }
}

// ---------------- pass D: per-bucket degree count + rank -> g_deg/g_dinv/g_rank
__global__ __launch_bounds__(512) void kD() {
    __shared__ int cnt[256];
    int b = blockIdx.x;
    int nbase = b * BKT_NODES;
    int nn = N_NODES - nbase; if (nn > BKT_NODES) nn = BKT_NODES;
    int astart = b * CAP;
    int ecnt = g_bcnt[b]; if (ecnt > CAP) ecnt = CAP;   // all threads read first
    int t = threadIdx.x;

    if (t < 256) cnt[t] = 0;
    __syncthreads();                 // barrier: every thread has banked ecnt
    if (t == 0) g_bcnt[b] = 0;       // reset for next replay (kA re-claims)

    for (int i = t; i < ecnt; i += 512) {
        int p = __ldg(&g_buf[astart + i]);
        int r = atomicAdd(&cnt[p >> 17], 1);
        g_rank[astart + i] = (unsigned char)r;   // within-node rank (coalesced)
    }
    __syncthreads();

    if (t < nn) {
        int d = cnt[t];
        g_deg[nbase + t]  = d;
        g_dinv[nbase + t] = rsqrtf((float)(d + 1));   // +1 self loop
    }
}

// ---------------- xw = x @ W, premultiplied fp16 messages ---------------------
__global__ __launch_bounds__(256) void k_xw(const float* __restrict__ x,
                                            const float* __restrict__ W) {
    __shared__ float4 sW4[16 * 32];
    for (int q = threadIdx.x; q < 512; q += 256) {
        int c = q >> 5, f = q & 31;
        sW4[q] = make_float4(W[(4 * f + 0) * HID + c], W[(4 * f + 1) * HID + c],
                             W[(4 * f + 2) * HID + c], W[(4 * f + 3) * HID + c]);
    }
    __syncthreads();

    int warp = (blockIdx.x * blockDim.x + threadIdx.x) >> 5;
    int lane = threadIdx.x & 31;
    int row  = warp * 4 + (lane >> 3);
    int sub  = lane & 7;
    if (row >= N_NODES) return;

    const float4* xr = reinterpret_cast<const float4*>(x + (size_t)row * NODE_DIM);
    float acc[16];
#pragma unroll
    for (int c = 0; c < 16; c++) acc[c] = 0.0f;

#pragma unroll
    for (int i = 0; i < 4; i++) {
        float4 xv = __ldg(&xr[sub * 4 + i]);
        int f = sub * 4 + i;
#pragma unroll
        for (int c = 0; c < 16; c++) {
            float4 wv = sW4[c * 32 + f];
            acc[c] += xv.x * wv.x + xv.y * wv.y + xv.z * wv.z + xv.w * wv.w;
        }
    }
#pragma unroll
    for (int off = 4; off; off >>= 1)
#pragma unroll
        for (int c = 0; c < 16; c++)
            acc[c] += __shfl_xor_sync(0xffffffffu, acc[c], off);

    if (sub == 0) {
        float di = g_dinv[row];
        __half2 h[8];
#pragma unroll
        for (int k = 0; k < 8; k++)
            h[k] = __floats2half2_rn(acc[2 * k] * di, acc[2 * k + 1] * di);
        uint4* o = reinterpret_cast<uint4*>(&g_xwh[(size_t)row * HID]);
        o[0] = *reinterpret_cast<uint4*>(&h[0]);
        o[1] = *reinterpret_cast<uint4*>(&h[4]);
    }
}

// ---------------- pass B: rank-indexed place (no atomics) + gather + finalize -
__global__ __launch_bounds__(512) void kB(const float* __restrict__ bias) {
    __shared__ int srcs[CAP];
    __shared__ int cnt[256];
    __shared__ int off[256];
    __shared__ int exc[256];
    __shared__ int wsum[8];

    int b = blockIdx.x;
    int nbase = b * BKT_NODES;
    int nn = N_NODES - nbase; if (nn > BKT_NODES) nn = BKT_NODES;
    int astart = b * CAP;
    int t = threadIdx.x;
    int lane = t & 31, w = t >> 5;

    // degrees + scan: first 256 threads only
    if (t < 256) {
        int c = (t < nn) ? __ldg(&g_deg[nbase + t]) : 0;
        cnt[t] = c;
        int incl = c;
#pragma unroll
        for (int o = 1; o < 32; o <<= 1) {
            int u = __shfl_up_sync(0xffffffffu, incl, o);
            if (lane >= o) incl += u;
        }
        if (lane == 31) wsum[w] = incl;
        __syncthreads();
        int pre = 0;
#pragma unroll
        for (int k = 0; k < 8; k++) pre += (k < w) ? wsum[k] : 0;
        off[t] = incl + pre;            // inclusive
        exc[t] = incl + pre - c;        // exclusive
    } else {
        __syncthreads();
    }
    __syncthreads();
    int ecnt = 0;
#pragma unroll
    for (int k = 0; k < 8; k++) ecnt += wsum[k];
    if (ecnt > CAP) ecnt = CAP;

    // place: rank-indexed, atomic-free, vectorized reads
    const int4*   buf4 = reinterpret_cast<const int4*>(&g_buf[astart]);
    const uchar4* rk4  = reinterpret_cast<const uchar4*>(&g_rank[astart]);
    int n4 = ecnt >> 2;
    for (int i = t; i < n4; i += 512) {
        int4   p = __ldg(&buf4[i]);
        uchar4 r = __ldg(&rk4[i]);
        srcs[exc[p.x >> 17] + r.x] = p.x & 0x1FFFF;
        srcs[exc[p.y >> 17] + r.y] = p.y & 0x1FFFF;
        srcs[exc[p.z >> 17] + r.z] = p.z & 0x1FFFF;
        srcs[exc[p.w >> 17] + r.w] = p.w & 0x1FFFF;
    }
    for (int i = (n4 << 2) + t; i < ecnt; i += 512) {
        int p = __ldg(&g_buf[astart + i]);
        srcs[exc[p >> 17] + __ldg(&g_rank[astart + i])] = p & 0x1FFFF;
    }
    __syncthreads();

    int sub = lane >> 2, part = lane & 3;
    const uint2* xh = reinterpret_cast<const uint2*>(g_xwh);

    for (int ln = w; ln < nn; ln += 16) {
        int deg  = cnt[ln];
        int base = off[ln] - deg;
        int end  = base + deg;
        float4 acc = make_float4(0.f, 0.f, 0.f, 0.f);
        int e = base + sub;
        // 4-deep unroll: 4 independent loads in flight
        for (; e + 24 < end; e += 32) {
            int s0 = srcs[e], s1 = srcs[e + 8], s2 = srcs[e + 16], s3 = srcs[e + 24];
            uint2 r0 = __ldg(&xh[(size_t)s0 * 4 + part]);
            uint2 r1 = __ldg(&xh[(size_t)s1 * 4 + part]);
            uint2 r2 = __ldg(&xh[(size_t)s2 * 4 + part]);
            uint2 r3 = __ldg(&xh[(size_t)s3 * 4 + part]);
            float2 a, bb;
            a = __half22float2(*reinterpret_cast<const __half2*>(&r0.x));
            bb = __half22float2(*reinterpret_cast<const __half2*>(&r0.y));
            acc.x += a.x; acc.y += a.y; acc.z += bb.x; acc.w += bb.y;
            a = __half22float2(*reinterpret_cast<const __half2*>(&r1.x));
            bb = __half22float2(*reinterpret_cast<const __half2*>(&r1.y));
            acc.x += a.x; acc.y += a.y; acc.z += bb.x; acc.w += bb.y;
            a = __half22float2(*reinterpret_cast<const __half2*>(&r2.x));
            bb = __half22float2(*reinterpret_cast<const __half2*>(&r2.y));
            acc.x += a.x; acc.y += a.y; acc.z += bb.x; acc.w += bb.y;
            a = __half22float2(*reinterpret_cast<const __half2*>(&r3.x));
            bb = __half22float2(*reinterpret_cast<const __half2*>(&r3.y));
            acc.x += a.x; acc.y += a.y; acc.z += bb.x; acc.w += bb.y;
        }
        for (; e < end; e += 8) {
            int s0 = srcs[e];
            uint2 r0 = __ldg(&xh[(size_t)s0 * 4 + part]);
            float2 a  = __half22float2(*reinterpret_cast<const __half2*>(&r0.x));
            float2 bb = __half22float2(*reinterpret_cast<const __half2*>(&r0.y));
            acc.x += a.x; acc.y += a.y; acc.z += bb.x; acc.w += bb.y;
        }
#pragma unroll
        for (int o = 4; o <= 16; o <<= 1) {
            acc.x += __shfl_xor_sync(0xffffffffu, acc.x, o);
            acc.y += __shfl_xor_sync(0xffffffffu, acc.y, o);
            acc.z += __shfl_xor_sync(0xffffffffu, acc.z, o);
            acc.w += __shfl_xor_sync(0xffffffffu, acc.w, o);
        }
        if (lane < 4) {
            int gn = nbase + ln;
            uint2 rw = xh[(size_t)gn * 4 + lane];          // self term (premult)
            float2 f0 = __half22float2(*reinterpret_cast<const __half2*>(&rw.x));
            float2 f1 = __half22float2(*reinterpret_cast<const __half2*>(&rw.y));
            float di = g_dinv[gn];
            float4 bv = __ldg(&reinterpret_cast<const float4*>(bias)[lane]);
            float4 o;
            o.x = fmaxf((acc.x + f0.x) * di + bv.x, 0.0f);
            o.y = fmaxf((acc.y + f0.y) * di + bv.y, 0.0f);
            o.z = fmaxf((acc.z + f1.x) * di + bv.z, 0.0f);
            o.w = fmaxf((acc.w + f1.y) * di + bv.w, 0.0f);
            reinterpret_cast<float4*>(g_agg)[(size_t)gn * 4 + lane] = o;
        }
    }
}

// ---------------- head: pool + modality FCs + classifier + log_softmax -------
__global__ __launch_bounds__(128) void k_head(
    const int* __restrict__ batch,
    const float* __restrict__ mri,  const float* __restrict__ cog,
    const float* __restrict__ clin, const float* __restrict__ gen,
    const float* __restrict__ mri_W, const float* __restrict__ mri_b,
    const float* __restrict__ cog_W, const float* __restrict__ cog_b,
    const float* __restrict__ clin_W, const float* __restrict__ clin_b,
    const float* __restrict__ gen_W, const float* __restrict__ gen_b,
    const float* __restrict__ W1, const float* __restrict__ b1,
    const float* __restrict__ W2, const float* __restrict__ b2,
    float* __restrict__ out)
{
    int g = blockIdx.x;
    int t = threadIdx.x;

    __shared__ int s_bounds[2];
    if (t < 2) {
        int target = g + t;
        int lo = 0, hi = N_NODES;
        while (lo < hi) {
            int mid = (lo + hi) >> 1;
            if (batch[mid] < target) lo = mid + 1; else hi = mid;
        }
        s_bounds[t] = lo;
    }
    __syncthreads();
    int start = s_bounds[0], end = s_bounds[1];

    float v[32];
#pragma unroll
    for (int j = 0; j < 32; j++) v[j] = 0.0f;

    for (int n = start + t; n < end; n += 128) {
        const float4* r = reinterpret_cast<const float4*>(&g_agg[(size_t)n * HID]);
        float4 a = r[0], b_ = r[1], c_ = r[2], d_ = r[3];
        v[0] += a.x;  v[1] += a.y;  v[2] += a.z;  v[3] += a.w;
        v[4] += b_.x; v[5] += b_.y; v[6] += b_.z; v[7] += b_.w;
        v[8] += c_.x; v[9] += c_.y; v[10]+= c_.z; v[11]+= c_.w;
        v[12]+= d_.x; v[13]+= d_.y; v[14]+= d_.z; v[15]+= d_.w;
    }
    {
        const float* row = mri + (size_t)g * MRI_DIM;
        for (int k = t; k < MRI_DIM; k += 128) {
            float x = __ldg(&row[k]);
#pragma unroll
            for (int c = 0; c < 4; c++) v[16 + c] += x * __ldg(&mri_W[k * 4 + c]);
        }
    }
    if (t < COG_DIM) {
        float x = __ldg(&cog[(size_t)g * COG_DIM + t]);
#pragma unroll
        for (int c = 0; c < 4; c++) v[20 + c] += x * __ldg(&cog_W[t * 4 + c]);
    }
    if (t < CLIN_DIM) {
        float x = __ldg(&clin[(size_t)g * CLIN_DIM + t]);
#pragma unroll
        for (int c = 0; c < 4; c++) v[24 + c] += x * __ldg(&clin_W[t * 4 + c]);
    }
    {
        const float* row = gen + (size_t)g * GEN_DIM;
        for (int k = t; k < GEN_DIM; k += 128) {
            float x = __ldg(&row[k]);
#pragma unroll
            for (int c = 0; c < 4; c++) v[28 + c] += x * __ldg(&gen_W[k * 4 + c]);
        }
    }

#pragma unroll
    for (int off = 16; off; off >>= 1)
#pragma unroll
        for (int j = 0; j < 32; j++)
            v[j] += __shfl_xor_sync(0xffffffffu, v[j], off);

    __shared__ float s_red[4][32];
    int warp = t >> 5, lane = t & 31;
    if (lane == 0)
#pragma unroll
        for (int j = 0; j < 32; j++) s_red[warp][j] = v[j];
    __syncthreads();

    __shared__ float s_comb[32];
    if (t < 32) {
        float val = s_red[0][t] + s_red[1][t] + s_red[2][t] + s_red[3][t];
        if (t < 16) {
            float cnt = fmaxf((float)(end - start), 1.0f);
            s_comb[t] = val / cnt;
        } else {
            int c = (t - 16) & 3;
            int m = (t - 16) >> 2;
            float bias = (m == 0) ? __ldg(&mri_b[c]) :
                         (m == 1) ? __ldg(&cog_b[c]) :
                         (m == 2) ? __ldg(&clin_b[c]) : __ldg(&gen_b[c]);
            s_comb[t] = fmaxf(val + bias, 0.0f);
        }
    }
    __syncthreads();

    __shared__ float s_h[16];
    if (t < 16) {
        float h = __ldg(&b1[t]);
#pragma unroll
        for (int i = 0; i < 32; i++) h += s_comb[i] * __ldg(&W1[i * 16 + t]);
        s_h[t] = fmaxf(h, 0.0f);
    }
    __syncthreads();

    __shared__ float s_lg[3];
    if (t < 3) {
        float lg = __ldg(&b2[t]);
#pragma unroll
        for (int j = 0; j < 16; j++) lg += s_h[j] * __ldg(&W2[j * 3 + t]);
        s_lg[t] = lg;
    }
    __syncthreads();

    if (t == 0) {
        float m = fmaxf(fmaxf(s_lg[0], s_lg[1]), s_lg[2]);
        float se = expf(s_lg[0] - m) + expf(s_lg[1] - m) + expf(s_lg[2] - m);
        float lse = m + logf(se);
        out[g * 3 + 0] = s_lg[0] - lse;
        out[g * 3 + 1] = s_lg[1] - lse;
        out[g * 3 + 2] = s_lg[2] - lse;
    }
}

// -----------------------------------------------------------------------------
extern "C" void kernel_launch(void* const* d_in, const int* in_sizes, int n_in,
                              void* d_out, int out_size) {
    const float* x      = (const float*)d_in[0];
    const int*   ei     = (const int*)d_in[1];
    const int*   batch  = (const int*)d_in[2];
    const float* mri    = (const float*)d_in[3];
    const float* cog    = (const float*)d_in[4];
    const float* clin   = (const float*)d_in[5];
    const float* gen    = (const float*)d_in[6];
    const float* gcn_W  = (const float*)d_in[7];
    const float* gcn_b  = (const float*)d_in[8];
    const float* mri_W  = (const float*)d_in[9];
    const float* mri_b  = (const float*)d_in[10];
    const float* cog_W  = (const float*)d_in[11];
    const float* cog_b  = (const float*)d_in[12];
    const float* clin_W = (const float*)d_in[13];
    const float* clin_b = (const float*)d_in[14];
    const float* gen_W  = (const float*)d_in[15];
    const float* gen_b  = (const float*)d_in[16];
    const float* W1     = (const float*)d_in[17];
    const float* b1     = (const float*)d_in[18];
    const float* W2     = (const float*)d_in[19];
    const float* b2     = (const float*)d_in[20];
    float* out = (float*)d_out;

    kA<<<ABLK, 512>>>(ei);                                   // 1
    kD<<<NBUSED, 512>>>();                                   // 2
    k_xw<<<(N_NODES + 31) / 32, 256>>>(x, gcn_W);            // 3
    kB<<<NBUSED, 512>>>(gcn_b);                              // 4  <- profiled
    k_head<<<N_GRAPHS, 128>>>(batch, mri, cog, clin, gen,    // 5
                              mri_W, mri_b, cog_W, cog_b, clin_W, clin_b,
                              gen_W, gen_b, W1, b1, W2, b2, out);
}

// round 16
// speedup vs baseline: 1.9255x; 1.0189x over previous
#include <cuda_runtime.h>
#include <cuda_fp16.h>
#include <math.h>

#define N_NODES   100000
#define N_EDGES   3200000
#define NODE_DIM  128
#define HID       16
#define N_GRAPHS  256
#define MRI_DIM   256
#define COG_DIM   64
#define CLIN_DIM  32
#define GEN_DIM   512

// bucketed counting sort
#define NBKT      512
#define BKT_NODES 196              // 511 buckets cover 100000 nodes
#define NBUSED    511
#define CAP       7680             // arena capacity per bucket (mean 6272, sigma ~79)
#define ABLK      800
#define AEDGES    4000             // 800 * 4000 = 3.2M exactly

// ---------------- device scratch ---------------------------------------------
__device__ __half        g_xwh[(size_t)N_NODES * HID]; // (x@W) * dinv (fp16 rows)
__device__ float         g_agg[(size_t)N_NODES * HID]; // relu(gcn output)
__device__ float         g_dinv[N_NODES];
__device__ int           g_deg[N_NODES];               // written fresh by kD
__device__ int           g_bcnt[NBKT];                 // arena counts (kD resets)
__device__ int           g_buf[(size_t)NBKT * CAP];    // packed (ldst<<17 | src)
__device__ unsigned char g_rank[(size_t)NBKT * CAP];   // within-node rank (kD)

// ---------------- pass A: bucket sort, hist-rank place (1 atomic pass) --------
__global__ __launch_bounds__(512) void kA(const int* __restrict__ ei) {
    __shared__ int            sp[AEDGES];
    __shared__ unsigned short sbr[AEDGES];   // (bucket<<7) | rank
    __shared__ int            sp2[AEDGES];
    __shared__ unsigned short sb2[AEDGES];
    __shared__ int hist[NBKT], startx[NBKT], basex[NBKT];
    __shared__ int wsum[16];

    int t = threadIdx.x;
    int lane = t & 31, w = t >> 5;
    int e0 = blockIdx.x * AEDGES;
    hist[t] = 0;
    __syncthreads();

    const int4* s4 = reinterpret_cast<const int4*>(ei + e0);
    const int4* d4 = reinterpret_cast<const int4*>(ei + N_EDGES + e0);
    for (int i = t; i < AEDGES / 4; i += 512) {
        int4 s = __ldg(&s4[i]);
        int4 d = __ldg(&d4[i]);
        int base = i << 2;
        unsigned b; int r;
        b = (unsigned)d.x / BKT_NODES; r = atomicAdd(&hist[b], 1);
        sp[base + 0] = ((d.x - (int)b * BKT_NODES) << 17) | s.x;
        sbr[base + 0] = (unsigned short)((b << 7) | r);
        b = (unsigned)d.y / BKT_NODES; r = atomicAdd(&hist[b], 1);
        sp[base + 1] = ((d.y - (int)b * BKT_NODES) << 17) | s.y;
        sbr[base + 1] = (unsigned short)((b << 7) | r);
        b = (unsigned)d.z / BKT_NODES; r = atomicAdd(&hist[b], 1);
        sp[base + 2] = ((d.z - (int)b * BKT_NODES) << 17) | s.z;
        sbr[base + 2] = (unsigned short)((b << 7) | r);
        b = (unsigned)d.w / BKT_NODES; r = atomicAdd(&hist[b], 1);
        sp[base + 3] = ((d.w - (int)b * BKT_NODES) << 17) | s.w;
        sbr[base + 3] = (unsigned short)((b << 7) | r);
    }
    __syncthreads();

    // warp-shfl inclusive scan over 512 buckets
    int c = hist[t];
    int incl = c;
#pragma unroll
    for (int o = 1; o < 32; o <<= 1) {
        int u = __shfl_up_sync(0xffffffffu, incl, o);
        if (lane >= o) incl += u;
    }
    if (lane == 31) wsum[w] = incl;
    __syncthreads();
    int pre = 0;
#pragma unroll
    for (int k = 0; k < 16; k++) pre += (k < w) ? wsum[k] : 0;
    basex[t] = (c > 0) ? (t * CAP + atomicAdd(&g_bcnt[t], c)) : 0;  // arena claim
    startx[t] = incl + pre - c;            // exclusive
    __syncthreads();

    // place into smem sorted-by-bucket order (atomic-free: rank-indexed)
    for (int i = t; i < AEDGES; i += 512) {
        int v = sbr[i];
        int b = v >> 7, r = v & 127;
        int j = startx[b] + r;
        sp2[j] = sp[i];
        sb2[j] = (unsigned short)b;
    }
    __syncthreads();

    // write out: consecutive j within a bucket run -> contiguous global span
    for (int j = t; j < AEDGES; j += 512) {
        int b = sb2[j];
        int pos = basex[b] + (j - startx[b]);
        if (pos < (b + 1) * CAP) g_buf[pos] = sp2[j];
    }
}

// ---------------- pass D: per-bucket degree count + rank -> g_deg/g_dinv/g_rank
__global__ __launch_bounds__(512) void kD() {
    __shared__ int cnt[256];
    int b = blockIdx.x;
    int nbase = b * BKT_NODES;
    int nn = N_NODES - nbase; if (nn > BKT_NODES) nn = BKT_NODES;
    int astart = b * CAP;
    int ecnt = g_bcnt[b]; if (ecnt > CAP) ecnt = CAP;   // all threads read first
    int t = threadIdx.x;

    if (t < 256) cnt[t] = 0;
    __syncthreads();                 // barrier: every thread has banked ecnt
    if (t == 0) g_bcnt[b] = 0;       // reset for next replay (kA re-claims)

    for (int i = t; i < ecnt; i += 512) {
        int p = __ldg(&g_buf[astart + i]);
        int r = atomicAdd(&cnt[p >> 17], 1);
        g_rank[astart + i] = (unsigned char)r;   // within-node rank (coalesced)
    }
    __syncthreads();

    if (t < nn) {
        int d = cnt[t];
        g_deg[nbase + t]  = d;
        g_dinv[nbase + t] = rsqrtf((float)(d + 1));   // +1 self loop
    }
}

// ---------------- xw = x @ W, premultiplied fp16 messages ---------------------
__global__ __launch_bounds__(256) void k_xw(const float* __restrict__ x,
                                            const float* __restrict__ W) {
    __shared__ float4 sW4[16 * 32];
    for (int q = threadIdx.x; q < 512; q += 256) {
        int c = q >> 5, f = q & 31;
        sW4[q] = make_float4(W[(4 * f + 0) * HID + c], W[(4 * f + 1) * HID + c],
                             W[(4 * f + 2) * HID + c], W[(4 * f + 3) * HID + c]);
    }
    __syncthreads();

    int warp = (blockIdx.x * blockDim.x + threadIdx.x) >> 5;
    int lane = threadIdx.x & 31;
    int row  = warp * 4 + (lane >> 3);
    int sub  = lane & 7;
    if (row >= N_NODES) return;

    const float4* xr = reinterpret_cast<const float4*>(x + (size_t)row * NODE_DIM);
    float acc[16];
#pragma unroll
    for (int c = 0; c < 16; c++) acc[c] = 0.0f;

#pragma unroll
    for (int i = 0; i < 4; i++) {
        float4 xv = __ldg(&xr[sub * 4 + i]);
        int f = sub * 4 + i;
#pragma unroll
        for (int c = 0; c < 16; c++) {
            float4 wv = sW4[c * 32 + f];
            acc[c] += xv.x * wv.x + xv.y * wv.y + xv.z * wv.z + xv.w * wv.w;
        }
    }
#pragma unroll
    for (int off = 4; off; off >>= 1)
#pragma unroll
        for (int c = 0; c < 16; c++)
            acc[c] += __shfl_xor_sync(0xffffffffu, acc[c], off);

    if (sub == 0) {
        float di = g_dinv[row];
        __half2 h[8];
#pragma unroll
        for (int k = 0; k < 8; k++)
            h[k] = __floats2half2_rn(acc[2 * k] * di, acc[2 * k + 1] * di);
        uint4* o = reinterpret_cast<uint4*>(&g_xwh[(size_t)row * HID]);
        o[0] = *reinterpret_cast<uint4*>(&h[0]);
        o[1] = *reinterpret_cast<uint4*>(&h[4]);
    }
}

// ---------------- pass B: rank-indexed place (no atomics) + gather + finalize -
__global__ __launch_bounds__(512) void kB(const float* __restrict__ bias) {
    __shared__ int srcs[CAP];
    __shared__ int cnt[256];
    __shared__ int off[256];
    __shared__ int exc[256];
    __shared__ int wsum[8];

    int b = blockIdx.x;
    int nbase = b * BKT_NODES;
    int nn = N_NODES - nbase; if (nn > BKT_NODES) nn = BKT_NODES;
    int astart = b * CAP;
    int t = threadIdx.x;
    int lane = t & 31, w = t >> 5;

    // degrees + scan: first 256 threads only
    if (t < 256) {
        int c = (t < nn) ? __ldg(&g_deg[nbase + t]) : 0;
        cnt[t] = c;
        int incl = c;
#pragma unroll
        for (int o = 1; o < 32; o <<= 1) {
            int u = __shfl_up_sync(0xffffffffu, incl, o);
            if (lane >= o) incl += u;
        }
        if (lane == 31) wsum[w] = incl;
        __syncthreads();
        int pre = 0;
#pragma unroll
        for (int k = 0; k < 8; k++) pre += (k < w) ? wsum[k] : 0;
        off[t] = incl + pre;            // inclusive
        exc[t] = incl + pre - c;        // exclusive
    } else {
        __syncthreads();
    }
    __syncthreads();
    int ecnt = 0;
#pragma unroll
    for (int k = 0; k < 8; k++) ecnt += wsum[k];
    if (ecnt > CAP) ecnt = CAP;

    // place: rank-indexed, atomic-free, vectorized reads
    const int4*   buf4 = reinterpret_cast<const int4*>(&g_buf[astart]);
    const uchar4* rk4  = reinterpret_cast<const uchar4*>(&g_rank[astart]);
    int n4 = ecnt >> 2;
    for (int i = t; i < n4; i += 512) {
        int4   p = __ldg(&buf4[i]);
        uchar4 r = __ldg(&rk4[i]);
        srcs[exc[p.x >> 17] + r.x] = p.x & 0x1FFFF;
        srcs[exc[p.y >> 17] + r.y] = p.y & 0x1FFFF;
        srcs[exc[p.z >> 17] + r.z] = p.z & 0x1FFFF;
        srcs[exc[p.w >> 17] + r.w] = p.w & 0x1FFFF;
    }
    for (int i = (n4 << 2) + t; i < ecnt; i += 512) {
        int p = __ldg(&g_buf[astart + i]);
        srcs[exc[p >> 17] + __ldg(&g_rank[astart + i])] = p & 0x1FFFF;
    }
    __syncthreads();

    int sub = lane >> 2, part = lane & 3;
    const uint2* xh = reinterpret_cast<const uint2*>(g_xwh);

    for (int ln = w; ln < nn; ln += 16) {
        int deg  = cnt[ln];
        int base = off[ln] - deg;
        int end  = base + deg;
        float4 acc = make_float4(0.f, 0.f, 0.f, 0.f);
        int e = base + sub;
        // 4-deep unroll: 4 independent loads in flight
        for (; e + 24 < end; e += 32) {
            int s0 = srcs[e], s1 = srcs[e + 8], s2 = srcs[e + 16], s3 = srcs[e + 24];
            uint2 r0 = __ldg(&xh[(size_t)s0 * 4 + part]);
            uint2 r1 = __ldg(&xh[(size_t)s1 * 4 + part]);
            uint2 r2 = __ldg(&xh[(size_t)s2 * 4 + part]);
            uint2 r3 = __ldg(&xh[(size_t)s3 * 4 + part]);
            float2 a, bb;
            a = __half22float2(*reinterpret_cast<const __half2*>(&r0.x));
            bb = __half22float2(*reinterpret_cast<const __half2*>(&r0.y));
            acc.x += a.x; acc.y += a.y; acc.z += bb.x; acc.w += bb.y;
            a = __half22float2(*reinterpret_cast<const __half2*>(&r1.x));
            bb = __half22float2(*reinterpret_cast<const __half2*>(&r1.y));
            acc.x += a.x; acc.y += a.y; acc.z += bb.x; acc.w += bb.y;
            a = __half22float2(*reinterpret_cast<const __half2*>(&r2.x));
            bb = __half22float2(*reinterpret_cast<const __half2*>(&r2.y));
            acc.x += a.x; acc.y += a.y; acc.z += bb.x; acc.w += bb.y;
            a = __half22float2(*reinterpret_cast<const __half2*>(&r3.x));
            bb = __half22float2(*reinterpret_cast<const __half2*>(&r3.y));
            acc.x += a.x; acc.y += a.y; acc.z += bb.x; acc.w += bb.y;
        }
        for (; e < end; e += 8) {
            int s0 = srcs[e];
            uint2 r0 = __ldg(&xh[(size_t)s0 * 4 + part]);
            float2 a  = __half22float2(*reinterpret_cast<const __half2*>(&r0.x));
            float2 bb = __half22float2(*reinterpret_cast<const __half2*>(&r0.y));
            acc.x += a.x; acc.y += a.y; acc.z += bb.x; acc.w += bb.y;
        }
#pragma unroll
        for (int o = 4; o <= 16; o <<= 1) {
            acc.x += __shfl_xor_sync(0xffffffffu, acc.x, o);
            acc.y += __shfl_xor_sync(0xffffffffu, acc.y, o);
            acc.z += __shfl_xor_sync(0xffffffffu, acc.z, o);
            acc.w += __shfl_xor_sync(0xffffffffu, acc.w, o);
        }
        if (lane < 4) {
            int gn = nbase + ln;
            uint2 rw = xh[(size_t)gn * 4 + lane];          // self term (premult)
            float2 f0 = __half22float2(*reinterpret_cast<const __half2*>(&rw.x));
            float2 f1 = __half22float2(*reinterpret_cast<const __half2*>(&rw.y));
            float di = g_dinv[gn];
            float4 bv = __ldg(&reinterpret_cast<const float4*>(bias)[lane]);
            float4 o;
            o.x = fmaxf((acc.x + f0.x) * di + bv.x, 0.0f);
            o.y = fmaxf((acc.y + f0.y) * di + bv.y, 0.0f);
            o.z = fmaxf((acc.z + f1.x) * di + bv.z, 0.0f);
            o.w = fmaxf((acc.w + f1.y) * di + bv.w, 0.0f);
            reinterpret_cast<float4*>(g_agg)[(size_t)gn * 4 + lane] = o;
        }
    }
}

// ---------------- head: pool + modality FCs + classifier + log_softmax -------
__global__ __launch_bounds__(128) void k_head(
    const int* __restrict__ batch,
    const float* __restrict__ mri,  const float* __restrict__ cog,
    const float* __restrict__ clin, const float* __restrict__ gen,
    const float* __restrict__ mri_W, const float* __restrict__ mri_b,
    const float* __restrict__ cog_W, const float* __restrict__ cog_b,
    const float* __restrict__ clin_W, const float* __restrict__ clin_b,
    const float* __restrict__ gen_W, const float* __restrict__ gen_b,
    const float* __restrict__ W1, const float* __restrict__ b1,
    const float* __restrict__ W2, const float* __restrict__ b2,
    float* __restrict__ out)
{
    int g = blockIdx.x;
    int t = threadIdx.x;

    __shared__ int s_bounds[2];
    if (t < 2) {
        int target = g + t;
        int lo = 0, hi = N_NODES;
        while (lo < hi) {
            int mid = (lo + hi) >> 1;
            if (batch[mid] < target) lo = mid + 1; else hi = mid;
        }
        s_bounds[t] = lo;
    }
    __syncthreads();
    int start = s_bounds[0], end = s_bounds[1];

    float v[32];
#pragma unroll
    for (int j = 0; j < 32; j++) v[j] = 0.0f;

    for (int n = start + t; n < end; n += 128) {
        const float4* r = reinterpret_cast<const float4*>(&g_agg[(size_t)n * HID]);
        float4 a = r[0], b_ = r[1], c_ = r[2], d_ = r[3];
        v[0] += a.x;  v[1] += a.y;  v[2] += a.z;  v[3] += a.w;
        v[4] += b_.x; v[5] += b_.y; v[6] += b_.z; v[7] += b_.w;
        v[8] += c_.x; v[9] += c_.y; v[10]+= c_.z; v[11]+= c_.w;
        v[12]+= d_.x; v[13]+= d_.y; v[14]+= d_.z; v[15]+= d_.w;
    }
    {
        const float* row = mri + (size_t)g * MRI_DIM;
        for (int k = t; k < MRI_DIM; k += 128) {
            float x = __ldg(&row[k]);
#pragma unroll
            for (int c = 0; c < 4; c++) v[16 + c] += x * __ldg(&mri_W[k * 4 + c]);
        }
    }
    if (t < COG_DIM) {
        float x = __ldg(&cog[(size_t)g * COG_DIM + t]);
#pragma unroll
        for (int c = 0; c < 4; c++) v[20 + c] += x * __ldg(&cog_W[t * 4 + c]);
    }
    if (t < CLIN_DIM) {
        float x = __ldg(&clin[(size_t)g * CLIN_DIM + t]);
#pragma unroll
        for (int c = 0; c < 4; c++) v[24 + c] += x * __ldg(&clin_W[t * 4 + c]);
    }
    {
        const float* row = gen + (size_t)g * GEN_DIM;
        for (int k = t; k < GEN_DIM; k += 128) {
            float x = __ldg(&row[k]);
#pragma unroll
            for (int c = 0; c < 4; c++) v[28 + c] += x * __ldg(&gen_W[k * 4 + c]);
        }
    }

#pragma unroll
    for (int off = 16; off; off >>= 1)
#pragma unroll
        for (int j = 0; j < 32; j++)
            v[j] += __shfl_xor_sync(0xffffffffu, v[j], off);

    __shared__ float s_red[4][32];
    int warp = t >> 5, lane = t & 31;
    if (lane == 0)
#pragma unroll
        for (int j = 0; j < 32; j++) s_red[warp][j] = v[j];
    __syncthreads();

    __shared__ float s_comb[32];
    if (t < 32) {
        float val = s_red[0][t] + s_red[1][t] + s_red[2][t] + s_red[3][t];
        if (t < 16) {
            float cnt = fmaxf((float)(end - start), 1.0f);
            s_comb[t] = val / cnt;
        } else {
            int c = (t - 16) & 3;
            int m = (t - 16) >> 2;
            float bias = (m == 0) ? __ldg(&mri_b[c]) :
                         (m == 1) ? __ldg(&cog_b[c]) :
                         (m == 2) ? __ldg(&clin_b[c]) : __ldg(&gen_b[c]);
            s_comb[t] = fmaxf(val + bias, 0.0f);
        }
    }
    __syncthreads();

    __shared__ float s_h[16];
    if (t < 16) {
        float h = __ldg(&b1[t]);
#pragma unroll
        for (int i = 0; i < 32; i++) h += s_comb[i] * __ldg(&W1[i * 16 + t]);
        s_h[t] = fmaxf(h, 0.0f);
    }
    __syncthreads();

    __shared__ float s_lg[3];
    if (t < 3) {
        float lg = __ldg(&b2[t]);
#pragma unroll
        for (int j = 0; j < 16; j++) lg += s_h[j] * __ldg(&W2[j * 3 + t]);
        s_lg[t] = lg;
    }
    __syncthreads();

    if (t == 0) {
        float m = fmaxf(fmaxf(s_lg[0], s_lg[1]), s_lg[2]);
        float se = expf(s_lg[0] - m) + expf(s_lg[1] - m) + expf(s_lg[2] - m);
        float lse = m + logf(se);
        out[g * 3 + 0] = s_lg[0] - lse;
        out[g * 3 + 1] = s_lg[1] - lse;
        out[g * 3 + 2] = s_lg[2] - lse;
    }
}

// -----------------------------------------------------------------------------
extern "C" void kernel_launch(void* const* d_in, const int* in_sizes, int n_in,
                              void* d_out, int out_size) {
    const float* x      = (const float*)d_in[0];
    const int*   ei     = (const int*)d_in[1];
    const int*   batch  = (const int*)d_in[2];
    const float* mri    = (const float*)d_in[3];
    const float* cog    = (const float*)d_in[4];
    const float* clin   = (const float*)d_in[5];
    const float* gen    = (const float*)d_in[6];
    const float* gcn_W  = (const float*)d_in[7];
    const float* gcn_b  = (const float*)d_in[8];
    const float* mri_W  = (const float*)d_in[9];
    const float* mri_b  = (const float*)d_in[10];
    const float* cog_W  = (const float*)d_in[11];
    const float* cog_b  = (const float*)d_in[12];
    const float* clin_W = (const float*)d_in[13];
    const float* clin_b = (const float*)d_in[14];
    const float* gen_W  = (const float*)d_in[15];
    const float* gen_b  = (const float*)d_in[16];
    const float* W1     = (const float*)d_in[17];
    const float* b1     = (const float*)d_in[18];
    const float* W2     = (const float*)d_in[19];
    const float* b2     = (const float*)d_in[20];
    float* out = (float*)d_out;

    kA<<<ABLK, 512>>>(ei);                                   // 1
    kD<<<NBUSED, 512>>>();                                   // 2
    k_xw<<<(N_NODES + 31) / 32, 256>>>(x, gcn_W);            // 3
    kB<<<NBUSED, 512>>>(gcn_b);                              // 4  <- profiled
    k_head<<<N_GRAPHS, 128>>>(batch, mri, cog, clin, gen,    // 5
                              mri_W, mri_b, cog_W, cog_b, clin_W, clin_b,
                              gen_W, gen_b, W1, b1, W2, b2, out);
}